// round 1
// baseline (speedup 1.0000x reference)
#include <cuda_runtime.h>
#include <math.h>

// ---------------- problem constants ----------------
#define B_SZ   512
#define SEQ    102
#define EMB    256
#define NH     16
#define HD     16
#define FFD    1024
#define NLAYER 3
#define KSZ    50
#define PSZ    1000
#define MTOK   (B_SZ*SEQ)      // 52224 tokens
#define OUTW   ((PSZ+1)*2)     // 2002

// ---------------- device scratch (static; no allocs allowed) ----------------
__device__ float g_X [MTOK*EMB];
__device__ float g_Q [MTOK*EMB];
__device__ float g_K [MTOK*EMB];
__device__ float g_V [MTOK*EMB];
__device__ float g_O [MTOK*EMB];
__device__ float g_X1[MTOK*EMB];
__device__ float g_H [MTOK*FFD];

// ---------------- build initial sequence ----------------
// out pos 0   = (x[b,50]  @ W_nv + b_nv)
// out pos 1..50  = x[b,0..49]
// out pos 51  = (x[b,101] @ W_v  + b_v)
// out pos 52..101 = x[b,51..100]
__global__ void build_kernel(const float* __restrict__ x,
                             const float* __restrict__ Wnv, const float* __restrict__ bnv,
                             const float* __restrict__ Wv,  const float* __restrict__ bv,
                             float* __restrict__ X)
{
    int b = blockIdx.x, p = blockIdx.y, t = threadIdx.x;   // 256 threads
    const float* xb = x + (size_t)b*SEQ*EMB;
    float* out = X + ((size_t)b*SEQ + p)*EMB;
    if (p == 0 || p == 51) {
        __shared__ float xs[EMB];
        const float* src = xb + (size_t)(p == 0 ? 50 : 101)*EMB;
        const float* W   = (p == 0) ? Wnv : Wv;
        const float* bb  = (p == 0) ? bnv : bv;
        xs[t] = src[t];
        __syncthreads();
        float acc = bb[t];
        #pragma unroll 8
        for (int k = 0; k < EMB; k++) acc = fmaf(xs[k], W[k*EMB + t], acc);
        out[t] = acc;
    } else {
        int srcp = p - 1;  // 1..50 -> 0..49 ; 52..101 -> 51..100
        out[t] = xb[(size_t)srcp*EMB + t];
    }
}

// ---------------- generic tiled fp32 GEMM ----------------
// C[M,N] = A[M,K] @ B[K,N]  (+bias[N]) (+res[M,N]) (relu?)
// BM=128 BN=64 BK=16, 256 threads, 8x4 per-thread microtile.
// Requires: M%128==0, N%64==0, K%16==0 (true for all call sites).
#define BM  128
#define BN  64
#define BKK 16

__global__ __launch_bounds__(256) void gemm_kernel(
    const float* __restrict__ A, const float* __restrict__ Bmat,
    const float* __restrict__ bias, const float* __restrict__ res,
    float* __restrict__ C, int M, int N, int K, int do_relu)
{
    __shared__ float As[BKK][BM+4];
    __shared__ float Bs[BKK][BN];
    const int bm = blockIdx.y * BM;
    const int bn = blockIdx.x * BN;
    const int t  = threadIdx.x;
    const int tm = t >> 4;      // 0..15
    const int tn = t & 15;      // 0..15

    float acc[8][4];
    #pragma unroll
    for (int r = 0; r < 8; r++)
        #pragma unroll
        for (int c = 0; c < 4; c++) acc[r][c] = 0.f;

    for (int k0 = 0; k0 < K; k0 += BKK) {
        // A tile: 128x16 = 512 float4s, 2 per thread (coalesced)
        #pragma unroll
        for (int i = 0; i < 2; i++) {
            int idx4 = t + i*256;
            int r  = idx4 >> 2;            // 0..127
            int c4 = (idx4 & 3) << 2;      // 0,4,8,12
            const float4 v = *(const float4*)(A + (size_t)(bm + r)*K + k0 + c4);
            As[c4+0][r] = v.x; As[c4+1][r] = v.y;
            As[c4+2][r] = v.z; As[c4+3][r] = v.w;
        }
        // B tile: 16x64 = 256 float4s, 1 per thread (coalesced)
        {
            int r  = t >> 4;               // 0..15
            int c4 = (t & 15) << 2;        // 0..60
            *(float4*)&Bs[r][c4] =
                *(const float4*)(Bmat + (size_t)(k0 + r)*N + bn + c4);
        }
        __syncthreads();
        #pragma unroll
        for (int kk = 0; kk < BKK; kk++) {
            float4 a0 = *(const float4*)&As[kk][tm*8];
            float4 a1 = *(const float4*)&As[kk][tm*8 + 4];
            float4 bv = *(const float4*)&Bs[kk][tn*4];
            float a[8] = {a0.x,a0.y,a0.z,a0.w,a1.x,a1.y,a1.z,a1.w};
            float bb[4] = {bv.x,bv.y,bv.z,bv.w};
            #pragma unroll
            for (int r = 0; r < 8; r++)
                #pragma unroll
                for (int c = 0; c < 4; c++)
                    acc[r][c] = fmaf(a[r], bb[c], acc[r][c]);
        }
        __syncthreads();
    }

    #pragma unroll
    for (int r = 0; r < 8; r++) {
        int row = bm + tm*8 + r;
        int col = bn + tn*4;
        float4 v = make_float4(acc[r][0], acc[r][1], acc[r][2], acc[r][3]);
        if (bias) {
            const float4 bb = *(const float4*)(bias + col);
            v.x += bb.x; v.y += bb.y; v.z += bb.z; v.w += bb.w;
        }
        if (res) {
            const float4 rr = *(const float4*)(res + (size_t)row*N + col);
            v.x += rr.x; v.y += rr.y; v.z += rr.z; v.w += rr.w;
        }
        if (do_relu) {
            v.x = fmaxf(v.x, 0.f); v.y = fmaxf(v.y, 0.f);
            v.z = fmaxf(v.z, 0.f); v.w = fmaxf(v.w, 0.f);
        }
        *(float4*)(C + (size_t)row*N + col) = v;
    }
}

// ---------------- attention: one block per (batch, head) ----------------
__global__ __launch_bounds__(128) void attn_kernel(
    const float* __restrict__ Q, const float* __restrict__ Kt,
    const float* __restrict__ V, float* __restrict__ O)
{
    int b = blockIdx.x, h = blockIdx.y, t = threadIdx.x;  // 128 threads
    __shared__ float Ks[SEQ][HD];
    __shared__ float Vs[SEQ][HD];
    size_t base = (size_t)b*SEQ*EMB + (size_t)h*HD;
    for (int idx = t; idx < SEQ*HD; idx += 128) {
        int n = idx >> 4, j = idx & 15;
        Ks[n][j] = Kt[base + (size_t)n*EMB + j];
        Vs[n][j] = V [base + (size_t)n*EMB + j];
    }
    __syncthreads();
    if (t < SEQ) {
        float q[HD];
        #pragma unroll
        for (int j = 0; j < HD; j++) q[j] = Q[base + (size_t)t*EMB + j] * 0.25f; // 1/sqrt(16)
        float mi = -1e30f, l = 0.f;
        float o[HD];
        #pragma unroll
        for (int j = 0; j < HD; j++) o[j] = 0.f;
        for (int m = 0; m < SEQ; m++) {
            float s = 0.f;
            #pragma unroll
            for (int j = 0; j < HD; j++) s = fmaf(q[j], Ks[m][j], s);
            float nm = fmaxf(mi, s);
            float sc = __expf(mi - nm);
            float p  = __expf(s  - nm);
            l = l*sc + p;
            #pragma unroll
            for (int j = 0; j < HD; j++) o[j] = o[j]*sc + p*Vs[m][j];
            mi = nm;
        }
        float inv = 1.f / l;
        #pragma unroll
        for (int j = 0; j < HD; j++) O[base + (size_t)t*EMB + j] = o[j]*inv;
    }
}

// ---------------- final: logits -> masked softmax -> props -> scatter ----------------
__global__ __launch_bounds__(128) void final_kernel(
    const float* __restrict__ X,  const float* __restrict__ Wf,
    const float* __restrict__ bf, const float* __restrict__ mask,
    const int* __restrict__ lastu, const int* __restrict__ depotu,
    float* __restrict__ out)
{
    int b = blockIdx.x, t = threadIdx.x;   // 128 threads
    __shared__ float lg[128];
    __shared__ float red[128];

    float acc = -INFINITY;
    if (t < SEQ) {
        const float4* r4 = (const float4*)(X + ((size_t)b*SEQ + t)*EMB);
        const float4* w4 = (const float4*)Wf;
        float s = bf[0];
        #pragma unroll 16
        for (int k = 0; k < EMB/4; k++) {
            float4 a = r4[k], w = w4[k];
            s = fmaf(a.x, w.x, s); s = fmaf(a.y, w.y, s);
            s = fmaf(a.z, w.z, s); s = fmaf(a.w, w.w, s);
        }
        if (t >= 1 && t <= KSZ) s += mask[(size_t)b*KSZ + (t-1)];
        if (t == 0 || t == KSZ+1) s = -INFINITY;
        acc = s;
    }
    lg[t] = acc;
    __syncthreads();

    // max reduce over 128 (dead lanes hold -inf)
    red[t] = lg[t];
    __syncthreads();
    #pragma unroll
    for (int s = 64; s > 0; s >>= 1) {
        if (t < s) red[t] = fmaxf(red[t], red[t+s]);
        __syncthreads();
    }
    float mx = red[0];
    __syncthreads();

    float e = 0.f;
    if (t < SEQ && t != 0 && t != KSZ+1) e = __expf(lg[t] - mx);
    red[t] = e;
    __syncthreads();
    #pragma unroll
    for (int s = 64; s > 0; s >>= 1) {
        if (t < s) red[t] += red[t+s];
        __syncthreads();
    }
    float inv = 1.f / red[0];
    __syncthreads();
    lg[t] = e * inv;   // props_full
    __syncthreads();

    // fill output row with 1e-20
    float* orow = out + (size_t)b*OUTW;
    for (int i = t; i < OUTW; i += 128) orow[i] = 1e-20f;
    __syncthreads();

    // scatter props
    if (t < KSZ) {
        float p1 = lg[1 + t];
        float p2 = lg[KSZ + 2 + t];
        if (p1 <= 1e-5f) p1 += 1e-7f;
        if (p2 <= 1e-5f) p2 += 1e-7f;
        orow[lastu[(size_t)b*KSZ + t]] = p1;
        orow[(PSZ + 1) + depotu[(size_t)b*KSZ + t]] = p2;
    }
}

// ---------------- launch ----------------
extern "C" void kernel_launch(void* const* d_in, const int* in_sizes, int n_in,
                              void* d_out, int out_size)
{
    (void)in_sizes; (void)n_in; (void)out_size;
    const float* x    = (const float*)d_in[0];
    const float* mask = (const float*)d_in[1];
    const float* Wnv  = (const float*)d_in[2];
    const float* bnv  = (const float*)d_in[3];
    const float* Wv_  = (const float*)d_in[4];
    const float* bv   = (const float*)d_in[5];
    const float* Wq   = (const float*)d_in[6];
    const float* Wk   = (const float*)d_in[7];
    const float* Wvp  = (const float*)d_in[8];
    const float* Wc   = (const float*)d_in[9];
    const float* bc   = (const float*)d_in[10];
    const float* W1   = (const float*)d_in[11];
    const float* b1   = (const float*)d_in[12];
    const float* W2   = (const float*)d_in[13];
    const float* b2   = (const float*)d_in[14];
    const float* Wf   = (const float*)d_in[15];
    const float* bf   = (const float*)d_in[16];
    const int*  lastu = (const int*)d_in[17];
    const int* depotu = (const int*)d_in[18];

    float *X, *Q, *K, *V, *O, *X1, *H;
    cudaGetSymbolAddress((void**)&X,  g_X);
    cudaGetSymbolAddress((void**)&Q,  g_Q);
    cudaGetSymbolAddress((void**)&K,  g_K);
    cudaGetSymbolAddress((void**)&V,  g_V);
    cudaGetSymbolAddress((void**)&O,  g_O);
    cudaGetSymbolAddress((void**)&X1, g_X1);
    cudaGetSymbolAddress((void**)&H,  g_H);

    // 1. build initial sequence
    build_kernel<<<dim3(B_SZ, SEQ), 256>>>(x, Wnv, bnv, Wv_, bv, X);

    dim3 gE(EMB/BN,  MTOK/BM);   // N=256
    dim3 gF(FFD/BN,  MTOK/BM);   // N=1024

    for (int l = 0; l < NLAYER; l++) {
        const float* wq = Wq + (size_t)l*EMB*EMB;
        const float* wk = Wk + (size_t)l*EMB*EMB;
        const float* wv = Wvp + (size_t)l*EMB*EMB;
        const float* wc = Wc + (size_t)l*EMB*EMB;
        const float* bcl = bc + (size_t)l*EMB;
        const float* w1 = W1 + (size_t)l*EMB*FFD;
        const float* b1l = b1 + (size_t)l*FFD;
        const float* w2 = W2 + (size_t)l*FFD*EMB;
        const float* b2l = b2 + (size_t)l*EMB;

        gemm_kernel<<<gE, 256>>>(X, wq, nullptr, nullptr, Q, MTOK, EMB, EMB, 0);
        gemm_kernel<<<gE, 256>>>(X, wk, nullptr, nullptr, K, MTOK, EMB, EMB, 0);
        gemm_kernel<<<gE, 256>>>(X, wv, nullptr, nullptr, V, MTOK, EMB, EMB, 0);
        attn_kernel<<<dim3(B_SZ, NH), 128>>>(Q, K, V, O);
        // out1 = X + O@Wc + bc
        gemm_kernel<<<gE, 256>>>(O, wc, bcl, X, X1, MTOK, EMB, EMB, 0);
        // H = relu(out1@W1 + b1)
        gemm_kernel<<<gF, 256>>>(X1, w1, b1l, nullptr, H, MTOK, FFD, EMB, 1);
        // X = out1 + H@W2 + b2
        gemm_kernel<<<gE, 256>>>(H, w2, b2l, X1, X, MTOK, EMB, FFD, 0);
    }

    final_kernel<<<B_SZ, 128>>>(X, Wf, bf, mask, lastu, depotu, (float*)d_out);
}